// round 2
// baseline (speedup 1.0000x reference)
#include <cuda_runtime.h>
#include <math_constants.h>

// out = minmax_normalize( bicubic_up2x( LL[:, 0:8] ) )
// All other terms of the reference iqwt are scaled by sum(gh)/sum(fl)/sum(fh),
// which are zero (|f32 residue| < 3e-7); the surviving term's scalar sg^2 > 0
// cancels in the (y-min)/(max-min) normalization.

#define THREADS 256
#define TILE_J  16            // input row-pairs per tile -> 32 output rows
#define IN_ROWS (TILE_J + 4)  // 20 input rows incl. halo
#define SMEM_W  260           // 256 cols + 2 halo each side
#define N_IN    256
#define N_OUT   512
#define N_IMG   64            // 8 batches * 8 channels (lglg slice)
#define TILES_PER_IMG 16
#define GRID (N_IMG * TILES_PER_IMG)

// bicubic a=-0.75 weights, src = 0.5*i - 0.25
// even output row 2j: taps at input rows j-2..j+1
#define WE0 (-0.03515625f)
#define WE1 ( 0.26171875f)
#define WE2 ( 0.87890625f)
#define WE3 (-0.10546875f)
// odd output row 2j+1: taps at input rows j-1..j+2
#define WO0 (-0.10546875f)
#define WO1 ( 0.87890625f)
#define WO2 ( 0.26171875f)
#define WO3 (-0.03515625f)

__device__ unsigned int g_minEnc;
__device__ unsigned int g_maxEnc;

__device__ __forceinline__ unsigned int encf(float f) {
    unsigned int u = __float_as_uint(f);
    return (u & 0x80000000u) ? ~u : (u | 0x80000000u);
}
__device__ __forceinline__ float decf(unsigned int e) {
    unsigned int u = (e & 0x80000000u) ? (e ^ 0x80000000u) : ~e;
    return __uint_as_float(u);
}

__global__ void qwt_init_kernel() {
    g_minEnc = 0xFFFFFFFFu;  // enc(+inf)-ish sentinel: larger than any enc
    g_maxEnc = 0u;
}

template <bool WRITE>
__global__ __launch_bounds__(THREADS)
void qwt_up_kernel(const float* __restrict__ LL, float* __restrict__ out) {
    __shared__ float s[IN_ROWS][SMEM_W];

    const int tid  = threadIdx.x;
    const int img  = blockIdx.x >> 4;        // 0..63
    const int tile = blockIdx.x & 15;        // 0..15
    const int b    = img >> 3;
    const int ch   = img & 7;                // lglg = LL channels 0..7
    const float* __restrict__ src = LL + (size_t)(b * 32 + ch) * (N_IN * N_IN);
    const int jbase = tile * TILE_J;

    float offset = 0.0f, scale = 1.0f;
    if (WRITE) {
        const float mn = decf(g_minEnc);
        const float mx = decf(g_maxEnc);
        offset = mn;
        scale  = 1.0f / (mx - mn);
    }

    // Fill 20x260 input tile with edge-clip (replicate) on rows and cols.
    for (int e = tid; e < IN_ROWS * SMEM_W; e += THREADS) {
        const int rr = e / SMEM_W;
        const int cc = e - rr * SMEM_W;
        int gr = jbase - 2 + rr; gr = min(max(gr, 0), N_IN - 1);
        int gc = cc - 2;         gc = min(max(gc, 0), N_IN - 1);
        s[rr][cc] = src[gr * N_IN + gc];
    }
    __syncthreads();

    // Horizontal pass: thread k produces output cols 2k, 2k+1 (input col k).
    const int k = tid;
    float he[IN_ROWS], ho[IN_ROWS];
#pragma unroll
    for (int rr = 0; rr < IN_ROWS; rr++) {
        const float z0 = s[rr][k + 0];
        const float z1 = s[rr][k + 1];
        const float z2 = s[rr][k + 2];
        const float z3 = s[rr][k + 3];
        const float z4 = s[rr][k + 4];
        he[rr] = WE0 * z0 + WE1 * z1 + WE2 * z2 + WE3 * z3;
        ho[rr] = WO0 * z1 + WO1 * z2 + WO2 * z3 + WO3 * z4;
    }

    float lmin =  CUDART_INF_F;
    float lmax = -CUDART_INF_F;
    const size_t obase = (size_t)img * (N_OUT * N_OUT);
    const int I0 = tile * (2 * TILE_J);

#pragma unroll
    for (int jj = 0; jj < TILE_J; jj++) {
        const float ee = WE0 * he[jj]     + WE1 * he[jj + 1] + WE2 * he[jj + 2] + WE3 * he[jj + 3];
        const float eo = WE0 * ho[jj]     + WE1 * ho[jj + 1] + WE2 * ho[jj + 2] + WE3 * ho[jj + 3];
        const float oe = WO0 * he[jj + 1] + WO1 * he[jj + 2] + WO2 * he[jj + 3] + WO3 * he[jj + 4];
        const float oo = WO0 * ho[jj + 1] + WO1 * ho[jj + 2] + WO2 * ho[jj + 3] + WO3 * ho[jj + 4];
        if (WRITE) {
            const int I = I0 + 2 * jj;
            float2 v0 = make_float2((ee - offset) * scale, (eo - offset) * scale);
            float2 v1 = make_float2((oe - offset) * scale, (oo - offset) * scale);
            *reinterpret_cast<float2*>(out + obase + (size_t)I * N_OUT + 2 * k)       = v0;
            *reinterpret_cast<float2*>(out + obase + (size_t)(I + 1) * N_OUT + 2 * k) = v1;
        } else {
            lmin = fminf(lmin, fminf(fminf(ee, eo), fminf(oe, oo)));
            lmax = fmaxf(lmax, fmaxf(fmaxf(ee, eo), fmaxf(oe, oo)));
        }
    }

    if (!WRITE) {
#pragma unroll
        for (int off = 16; off > 0; off >>= 1) {
            lmin = fminf(lmin, __shfl_xor_sync(0xFFFFFFFFu, lmin, off));
            lmax = fmaxf(lmax, __shfl_xor_sync(0xFFFFFFFFu, lmax, off));
        }
        __shared__ float wmin[THREADS / 32], wmax[THREADS / 32];
        const int w = tid >> 5, l = tid & 31;
        if (l == 0) { wmin[w] = lmin; wmax[w] = lmax; }
        __syncthreads();
        if (tid == 0) {
            float m = wmin[0], M = wmax[0];
#pragma unroll
            for (int i = 1; i < THREADS / 32; i++) {
                m = fminf(m, wmin[i]);
                M = fmaxf(M, wmax[i]);
            }
            atomicMin(&g_minEnc, encf(m));
            atomicMax(&g_maxEnc, encf(M));
        }
    }
}

extern "C" void kernel_launch(void* const* d_in, const int* in_sizes, int n_in,
                              void* d_out, int out_size) {
    const float* LL = (const float*)d_in[0];
    float* out = (float*)d_out;
    (void)in_sizes; (void)n_in; (void)out_size;

    qwt_init_kernel<<<1, 1>>>();
    qwt_up_kernel<false><<<GRID, THREADS>>>(LL, out);  // min/max pass
    qwt_up_kernel<true ><<<GRID, THREADS>>>(LL, out);  // normalize + write pass
}